// round 11
// baseline (speedup 1.0000x reference)
#include <cuda_runtime.h>
#include <cuda_fp16.h>
#include <math.h>
#include <stdint.h>

// Problem constants
#define B_    4
#define T_    2048
#define HID_  2048
#define NH    16
#define NKV   2
#define HD_   128
#define MROWS (B_ * T_)   // 8192

// fp16 scratch (allocation-free rule: __device__ globals)
__device__ __half g_xh  [(size_t)MROWS * HID_];
__device__ __half g_wqh [(size_t)HID_ * HID_];
__device__ __half g_wkvh[(size_t)2 * NKV * HD_ * HID_];   // Wk rows 0-255, Wv rows 256-511
__device__ __half g_woh [(size_t)HID_ * HID_];
__device__ __half g_qh  [(size_t)MROWS * HID_];
__device__ __half g_kvh [(size_t)MROWS * 2 * NKV * HD_];  // [row, 512]: k@g*128, v@256+g*128
__device__ __half g_yh  [(size_t)MROWS * HID_];

// ---------------------------------------------------------------------------
// Helpers
// ---------------------------------------------------------------------------
__device__ __forceinline__ uint32_t packh2(float lo, float hi) {
    __half2 h = __floats2half2_rn(lo, hi);
    return *(uint32_t*)&h;
}

__device__ __forceinline__ void mma_f16(float c[4],
                                        uint32_t a0, uint32_t a1, uint32_t a2, uint32_t a3,
                                        uint32_t b0, uint32_t b1) {
    asm volatile(
        "mma.sync.aligned.m16n8k16.row.col.f32.f16.f16.f32 "
        "{%0,%1,%2,%3}, {%4,%5,%6,%7}, {%8,%9}, {%0,%1,%2,%3};"
        : "+f"(c[0]), "+f"(c[1]), "+f"(c[2]), "+f"(c[3])
        : "r"(a0), "r"(a1), "r"(a2), "r"(a3), "r"(b0), "r"(b1));
}

#define LDMX4(r0, r1, r2, r3, addr)                                             \
    asm volatile("ldmatrix.sync.aligned.m8n8.x4.shared.b16 {%0,%1,%2,%3}, [%4];" \
                 : "=r"(r0), "=r"(r1), "=r"(r2), "=r"(r3) : "r"(addr))

#define LDMX4T(r0, r1, r2, r3, addr)                                                  \
    asm volatile("ldmatrix.sync.aligned.m8n8.x4.trans.shared.b16 {%0,%1,%2,%3}, [%4];" \
                 : "=r"(r0), "=r"(r1), "=r"(r2), "=r"(r3) : "r"(addr))

#define CPA16(dst, src) \
    asm volatile("cp.async.cg.shared.global [%0], [%1], 16;" :: "r"(dst), "l"(src))
#define CP_COMMIT() asm volatile("cp.async.commit_group;" ::: "memory")
#define CP_WAIT(n)  asm volatile("cp.async.wait_group %0;" :: "n"(n) : "memory")

// ---------------------------------------------------------------------------
// Fused fp32 -> fp16 convert for all 5 buffers (one launch).
// ---------------------------------------------------------------------------
#define C_X  (MROWS * HID_ / 4)                  // 4194304
#define C_WQ (HID_ * HID_ / 4)                   // 1048576
#define C_WK (NKV * HD_ * HID_ / 4)              // 131072
#define C_TOT (C_X + 2 * C_WQ + 2 * C_WK)        // 6553600

__global__ __launch_bounds__(256) void cvt_all(const float* __restrict__ x,
                                               const float* __restrict__ Wq,
                                               const float* __restrict__ Wk,
                                               const float* __restrict__ Wv,
                                               const float* __restrict__ Wo,
                                               __half* __restrict__ xh,
                                               __half* __restrict__ wqh,
                                               __half* __restrict__ wkvh,
                                               __half* __restrict__ woh) {
    int i = blockIdx.x * 256 + threadIdx.x;
    const float* src;
    __half* dst;
    int off;
    if (i < C_X)                        { src = x;  dst = xh;  off = i; }
    else if ((i -= C_X) < C_WQ)         { src = Wq; dst = wqh; off = i; }
    else if ((i -= C_WQ) < C_WK)        { src = Wk; dst = wkvh; off = i; }
    else if ((i -= C_WK) < C_WK)        { src = Wv; dst = wkvh + (size_t)NKV * HD_ * HID_; off = i; }
    else if ((i -= C_WK) < C_WQ)        { src = Wo; dst = woh; off = i; }
    else return;
    float4 v = ((const float4*)src)[off];
    uint2 o = {packh2(v.x, v.y), packh2(v.z, v.w)};
    ((uint2*)dst)[off] = o;
}

// ---------------------------------------------------------------------------
// FP16 GEMM (NT), 128x256x64 CTA tile, 3-stage cp.async pipeline.
// 256 threads = 8 warps as 2(m) x 4(n); warp tile 64x64.
// Per k16: 8 LDSM.x4 -> 32 MMA.
// Per stage: A = 128 rows x 8 chunks (1024), B = 256 rows x 8 chunks (2048).
// ---------------------------------------------------------------------------
#define GST 36                              // words per 64-half row (32+4 pad)
#define STG_A_W (128 * GST)                 // 4608
#define STG_B_W (256 * GST)                 // 9216
#define STAGE_BYTES ((STG_A_W + STG_B_W) * 4)   // 55296
#define GSMEM (3 * STAGE_BYTES)             // 165888

__global__ __launch_bounds__(256) void f16_gemm_pipe(const __half* __restrict__ A,
                                                     const __half* __restrict__ Bw,
                                                     void* __restrict__ Cout,
                                                     int M, int N, int K, int out_half) {
    extern __shared__ uint32_t su[];
    const uint32_t sbase = (uint32_t)__cvta_generic_to_shared(su);

    const int tid  = threadIdx.x;
    const int lane = tid & 31, warp = tid >> 5;
    const int gid  = lane >> 2, tig = lane & 3;
    const int wm   = (warp >> 2) * 64;      // 0 or 64
    const int wn   = (warp & 3) * 64;       // 0..192
    const int bm   = blockIdx.y * 128;
    const int bn   = blockIdx.x * 256;

    const int a_row = (lane & 7) + ((lane >> 3) & 1) * 8;
    const int a_cw  = (lane >> 4) * 4;
    const int b_row = (lane & 7) + (lane >> 4) * 8;
    const int b_cw  = ((lane >> 3) & 1) * 4;

    const int S = K >> 6;

    auto issue = [&](int s, int buf) {
        const int k0 = s << 6;
        const uint32_t abase = sbase + buf * STAGE_BYTES;
        const uint32_t bbase = abase + STG_A_W * 4;
#pragma unroll
        for (int i = 0; i < 4; i++) {       // A: 1024 chunks
            int idx = i * 256 + tid;
            int r = idx >> 3, cq = idx & 7;
            CPA16(abase + (r * GST + cq * 4) * 4,
                  A + (size_t)(bm + r) * K + k0 + cq * 8);
        }
#pragma unroll
        for (int i = 0; i < 8; i++) {       // B: 2048 chunks
            int idx = i * 256 + tid;
            int r = idx >> 3, cq = idx & 7;
            CPA16(bbase + (r * GST + cq * 4) * 4,
                  Bw + (size_t)(bn + r) * K + k0 + cq * 8);
        }
        CP_COMMIT();
    };

    float acc[4][8][4] = {};

    issue(0, 0);
    issue(1, 1);

    for (int s = 0; s < S; s++) {
        CP_WAIT(1);
        __syncthreads();
        if (s + 2 < S) issue(s + 2, (s + 2) % 3);

        const uint32_t abase = sbase + (s % 3) * STAGE_BYTES;
        const uint32_t bbase = abase + STG_A_W * 4;
#pragma unroll
        for (int kk = 0; kk < 4; kk++) {
            uint32_t af[4][4], bf[8][2];
#pragma unroll
            for (int mi = 0; mi < 4; mi++) {
                uint32_t addr = abase + (((wm + mi * 16 + a_row) * GST + kk * 8 + a_cw) << 2);
                LDMX4(af[mi][0], af[mi][1], af[mi][2], af[mi][3], addr);
            }
#pragma unroll
            for (int nb = 0; nb < 4; nb++) {
                uint32_t addr = bbase + (((wn + nb * 16 + b_row) * GST + kk * 8 + b_cw) << 2);
                LDMX4(bf[2 * nb][0], bf[2 * nb][1], bf[2 * nb + 1][0], bf[2 * nb + 1][1], addr);
            }
#pragma unroll
            for (int mi = 0; mi < 4; mi++)
#pragma unroll
                for (int ni = 0; ni < 8; ni++)
                    mma_f16(acc[mi][ni], af[mi][0], af[mi][1], af[mi][2], af[mi][3],
                            bf[ni][0], bf[ni][1]);
        }
    }

#pragma unroll
    for (int mi = 0; mi < 4; mi++)
#pragma unroll
        for (int ni = 0; ni < 8; ni++) {
            int row = bm + wm + mi * 16 + gid;
            int col = bn + wn + ni * 8 + 2 * tig;
            if (out_half) {
                __half* Ch = (__half*)Cout;
                *(uint32_t*)(Ch + (size_t)row * N + col) =
                    packh2(acc[mi][ni][0], acc[mi][ni][1]);
                *(uint32_t*)(Ch + (size_t)(row + 8) * N + col) =
                    packh2(acc[mi][ni][2], acc[mi][ni][3]);
            } else {
                float* Cf = (float*)Cout;
                float2 lo = {acc[mi][ni][0], acc[mi][ni][1]};
                float2 hi = {acc[mi][ni][2], acc[mi][ni][3]};
                *(float2*)(Cf + (size_t)row * N + col)       = lo;
                *(float2*)(Cf + (size_t)(row + 8) * N + col) = hi;
            }
        }
}

// ---------------------------------------------------------------------------
// Fused RoPE + RMSNorm on fp16 (fp32 math). One warp per 128-elem head row.
// ---------------------------------------------------------------------------
__global__ __launch_bounds__(256) void rope_rms_h(__half* __restrict__ q,
                                                  __half* __restrict__ kv,
                                                  const float* __restrict__ cosp,
                                                  const float* __restrict__ sinp) {
    int gw   = (blockIdx.x * 256 + threadIdx.x) >> 5;
    int lane = threadIdx.x & 31;
    const int QROWS = MROWS * NH;
    const int KROWS = MROWS * NKV;

    __half* hp;
    int t;
    if (gw < QROWS) {
        t = (gw >> 4) & (T_ - 1);
        hp = q + (size_t)gw * HD_;
    } else {
        int r = gw - QROWS;
        if (r >= KROWS) return;
        t = (r >> 1) & (T_ - 1);
        hp = kv + (size_t)(r >> 1) * 512 + (r & 1) * 128;
    }
    uint32_t* ptr = (uint32_t*)hp;

    float2 x0 = __half22float2(*(__half2*)&ptr[lane]);
    float2 x1 = __half22float2(*(__half2*)&ptr[lane + 32]);
    float c0  = cosp[t * 64 + lane],      sn0 = sinp[t * 64 + lane];
    float c1  = cosp[t * 64 + lane + 32], sn1 = sinp[t * 64 + lane + 32];

    float o0r = x0.x * c0 - x0.y * sn0;
    float o0i = x0.x * sn0 + x0.y * c0;
    float o1r = x1.x * c1 - x1.y * sn1;
    float o1i = x1.x * sn1 + x1.y * c1;

    float ss = o0r * o0r + o0i * o0i + o1r * o1r + o1i * o1i;
#pragma unroll
    for (int off = 16; off > 0; off >>= 1)
        ss += __shfl_xor_sync(0xffffffffu, ss, off);
    float sc = rsqrtf(ss * (1.0f / 128.0f) + 1.1920929e-7f);

    ptr[lane]      = packh2(o0r * sc, o0i * sc);
    ptr[lane + 32] = packh2(o1r * sc, o1i * sc);
}

// ---------------------------------------------------------------------------
// FP16 flash attention (causal, GQA 8:1), 128 q x 128 kv tiles. (as R9)
// ---------------------------------------------------------------------------
#define FH    68
#define OFF_K0 (128 * FH)
#define KVBUF  (2 * 128 * FH)
#define FLASH_SMEM_BYTES ((OFF_K0 + 2 * KVBUF) * 4)   // 174080

__global__ __launch_bounds__(256) void flash_h(const __half* __restrict__ Q,
                                               const __half* __restrict__ KV,
                                               __half* __restrict__ Y) {
    extern __shared__ uint32_t su[];
    const uint32_t qs_b = (uint32_t)__cvta_generic_to_shared(su);

    const int bx = blockIdx.x, h = blockIdx.y, b = blockIdx.z;
    const int g = h >> 3;
    const int tid = threadIdx.x, warp = tid >> 5, lane = tid & 31;
    const int gid = lane >> 2, tig = lane & 3;
    const int q0 = bx * 128;
    const int w16 = warp * 16;
    const float scale = 0.08838834764831845f;

    const int a_row = (lane & 7) + ((lane >> 3) & 1) * 8;
    const int a_cw  = (lane >> 4) * 4;
    const int kb_row = (lane & 7) + (lane >> 4) * 8;
    const int kb_cw  = ((lane >> 3) & 1) * 4;
    const int vb_row = (lane & 7) + ((lane >> 3) & 1) * 8;
    const int vb_cw  = (lane >> 4) * 4;

    const int nkv = bx + 1;

    auto issue_kv = [&](int kt, int buf) {
        const uint32_t kbase = qs_b + (OFF_K0 + buf * KVBUF) * 4;
        const uint32_t vbase = kbase + 128 * FH * 4;
#pragma unroll
        for (int i = 0; i < 8; i++) {
            int idx = i * 256 + tid;
            int row = idx >> 4, cq = idx & 15;
            size_t base = (size_t)(b * T_ + kt * 128 + row) * 512 + g * 128 + cq * 8;
            CPA16(kbase + (row * FH + cq * 4) * 4, KV + base);
            CPA16(vbase + (row * FH + cq * 4) * 4, KV + base + 256);
        }
        CP_COMMIT();
    };

    issue_kv(0, 0);

#pragma unroll
    for (int i = 0; i < 8; i++) {
        int idx = i * 256 + tid;
        int row = idx >> 4, cq = idx & 15;
        *(uint4*)&su[row * FH + cq * 4] =
            *(const uint4*)(Q + ((size_t)((b * T_ + q0 + row) * NH + h)) * HD_ + cq * 8);
    }

    float m0 = -INFINITY, m1 = -INFINITY, l0 = 0.0f, l1 = 0.0f;
    float O[16][4];
#pragma unroll
    for (int ni = 0; ni < 16; ni++)
        O[ni][0] = O[ni][1] = O[ni][2] = O[ni][3] = 0.0f;

    for (int kt = 0; kt < nkv; kt++) {
        const int buf = kt & 1;
        CP_WAIT(0);
        __syncthreads();
        if (kt + 1 < nkv) issue_kv(kt + 1, buf ^ 1);

        const uint32_t ks_b = qs_b + (OFF_K0 + buf * KVBUF) * 4;
        const uint32_t vs_b = ks_b + 128 * FH * 4;

        float s[16][4] = {};
#pragma unroll
        for (int kk = 0; kk < 8; kk++) {
            uint32_t a0, a1, a2, a3;
            LDMX4(a0, a1, a2, a3, qs_b + (((w16 + a_row) * FH + kk * 8 + a_cw) << 2));
#pragma unroll
            for (int nb = 0; nb < 8; nb++) {
                uint32_t b0, b1, b2, b3;
                LDMX4(b0, b1, b2, b3,
                      ks_b + (((nb * 16 + kb_row) * FH + kk * 8 + kb_cw) << 2));
                mma_f16(s[2 * nb],     a0, a1, a2, a3, b0, b1);
                mma_f16(s[2 * nb + 1], a0, a1, a2, a3, b2, b3);
            }
        }
#pragma unroll
        for (int ni = 0; ni < 16; ni++) {
            s[ni][0] *= scale; s[ni][1] *= scale;
            s[ni][2] *= scale; s[ni][3] *= scale;
        }

        if (kt == bx) {
            int r_lo = w16 + gid, r_hi = r_lo + 8;
#pragma unroll
            for (int ni = 0; ni < 16; ni++) {
                int col = ni * 8 + 2 * tig;
                if (col     > r_lo) s[ni][0] = -INFINITY;
                if (col + 1 > r_lo) s[ni][1] = -INFINITY;
                if (col     > r_hi) s[ni][2] = -INFINITY;
                if (col + 1 > r_hi) s[ni][3] = -INFINITY;
            }
        }

        float mx0 = -INFINITY, mx1 = -INFINITY;
#pragma unroll
        for (int ni = 0; ni < 16; ni++) {
            mx0 = fmaxf(mx0, fmaxf(s[ni][0], s[ni][1]));
            mx1 = fmaxf(mx1, fmaxf(s[ni][2], s[ni][3]));
        }
        mx0 = fmaxf(mx0, __shfl_xor_sync(0xffffffffu, mx0, 1));
        mx0 = fmaxf(mx0, __shfl_xor_sync(0xffffffffu, mx0, 2));
        mx1 = fmaxf(mx1, __shfl_xor_sync(0xffffffffu, mx1, 1));
        mx1 = fmaxf(mx1, __shfl_xor_sync(0xffffffffu, mx1, 2));

        float mn0 = fmaxf(m0, mx0), mn1 = fmaxf(m1, mx1);
        float al0 = __expf(m0 - mn0), al1 = __expf(m1 - mn1);
        m0 = mn0; m1 = mn1;

        float ps0 = 0.0f, ps1 = 0.0f;
#pragma unroll
        for (int ni = 0; ni < 16; ni++) {
            s[ni][0] = __expf(s[ni][0] - mn0);
            s[ni][1] = __expf(s[ni][1] - mn0);
            s[ni][2] = __expf(s[ni][2] - mn1);
            s[ni][3] = __expf(s[ni][3] - mn1);
            ps0 += s[ni][0] + s[ni][1];
            ps1 += s[ni][2] + s[ni][3];
        }
        ps0 += __shfl_xor_sync(0xffffffffu, ps0, 1);
        ps0 += __shfl_xor_sync(0xffffffffu, ps0, 2);
        ps1 += __shfl_xor_sync(0xffffffffu, ps1, 1);
        ps1 += __shfl_xor_sync(0xffffffffu, ps1, 2);
        l0 = l0 * al0 + ps0;
        l1 = l1 * al1 + ps1;

#pragma unroll
        for (int ni = 0; ni < 16; ni++) {
            O[ni][0] *= al0; O[ni][1] *= al0;
            O[ni][2] *= al1; O[ni][3] *= al1;
        }

#pragma unroll
        for (int j = 0; j < 8; j++) {
            uint32_t a0 = packh2(s[2 * j][0],     s[2 * j][1]);
            uint32_t a1 = packh2(s[2 * j][2],     s[2 * j][3]);
            uint32_t a2 = packh2(s[2 * j + 1][0], s[2 * j + 1][1]);
            uint32_t a3 = packh2(s[2 * j + 1][2], s[2 * j + 1][3]);
#pragma unroll
            for (int nb = 0; nb < 8; nb++) {
                uint32_t b0, b1, b2, b3;
                LDMX4T(b0, b1, b2, b3,
                       vs_b + (((j * 16 + vb_row) * FH + nb * 8 + vb_cw) << 2));
                mma_f16(O[2 * nb],     a0, a1, a2, a3, b0, b1);
                mma_f16(O[2 * nb + 1], a0, a1, a2, a3, b2, b3);
            }
        }
    }

    float inv0 = 1.0f / l0, inv1 = 1.0f / l1;
    int row0 = q0 + w16 + gid, row1 = row0 + 8;
#pragma unroll
    for (int ni = 0; ni < 16; ni++) {
        int col = ni * 8 + 2 * tig;
        *(uint32_t*)(Y + ((size_t)((b * T_ + row0) * NH + h)) * HD_ + col) =
            packh2(O[ni][0] * inv0, O[ni][1] * inv0);
        *(uint32_t*)(Y + ((size_t)((b * T_ + row1) * NH + h)) * HD_ + col) =
            packh2(O[ni][2] * inv1, O[ni][3] * inv1);
    }
}

// ---------------------------------------------------------------------------
// Launch
// ---------------------------------------------------------------------------
extern "C" void kernel_launch(void* const* d_in, const int* in_sizes, int n_in,
                              void* d_out, int out_size) {
    const float* x    = (const float*)d_in[0];
    const float* cosp = (const float*)d_in[1];
    const float* sinp = (const float*)d_in[2];
    const float* Wq   = (const float*)d_in[3];
    const float* Wk   = (const float*)d_in[4];
    const float* Wv   = (const float*)d_in[5];
    const float* Wo   = (const float*)d_in[6];
    float* out = (float*)d_out;

    __half *xh, *wqh, *wkvh, *woh, *qh, *kvh, *yh;
    cudaGetSymbolAddress((void**)&xh,   g_xh);
    cudaGetSymbolAddress((void**)&wqh,  g_wqh);
    cudaGetSymbolAddress((void**)&wkvh, g_wkvh);
    cudaGetSymbolAddress((void**)&woh,  g_woh);
    cudaGetSymbolAddress((void**)&qh,   g_qh);
    cudaGetSymbolAddress((void**)&kvh,  g_kvh);
    cudaGetSymbolAddress((void**)&yh,   g_yh);

    cudaFuncSetAttribute(f16_gemm_pipe, cudaFuncAttributeMaxDynamicSharedMemorySize, GSMEM);
    cudaFuncSetAttribute(flash_h, cudaFuncAttributeMaxDynamicSharedMemorySize,
                         FLASH_SMEM_BYTES);

    dim3 blk(256);
    const int KVN = 2 * NKV * HD_;   // 512
    // One fused fp32 -> fp16 convert for x + all weights
    cvt_all<<<(C_TOT + 255) / 256, blk>>>(x, Wq, Wk, Wv, Wo, xh, wqh, wkvh, woh);

    // Projections (fp16 mma.sync, 128x256 tiles, cp.async pipelined)
    f16_gemm_pipe<<<dim3(HID_ / 256, MROWS / 128), blk, GSMEM>>>(xh, wqh, qh, MROWS, HID_, HID_, 1);
    f16_gemm_pipe<<<dim3(KVN / 256, MROWS / 128), blk, GSMEM>>>(xh, wkvh, kvh, MROWS, KVN, HID_, 1);
    // RoPE + RMSNorm (fp16 in/out, fp32 math)
    rope_rms_h<<<(MROWS * (NH + NKV)) / 8, blk>>>(qh, kvh, cosp, sinp);
    // Flash attention (fp16 mma.sync, BKV=128, cp.async double-buffered KV)
    flash_h<<<dim3(T_ / 128, NH, B_), blk, FLASH_SMEM_BYTES>>>(qh, kvh, yh);
    // Output projection -> fp32 out
    f16_gemm_pipe<<<dim3(HID_ / 256, MROWS / 128), blk, GSMEM>>>(yh, woh, out, MROWS, HID_, HID_, 0);
}

// round 14
// speedup vs baseline: 1.0699x; 1.0699x over previous
#include <cuda_runtime.h>
#include <cuda_fp16.h>
#include <math.h>
#include <stdint.h>

// Problem constants
#define B_    4
#define T_    2048
#define HID_  2048
#define NH    16
#define NKV   2
#define HD_   128
#define MROWS (B_ * T_)   // 8192

// fp16 scratch (allocation-free rule: __device__ globals)
__device__ __half g_xh  [(size_t)MROWS * HID_];
__device__ __half g_wqh [(size_t)HID_ * HID_];
__device__ __half g_wkvh[(size_t)2 * NKV * HD_ * HID_];   // Wk rows 0-255, Wv rows 256-511
__device__ __half g_woh [(size_t)HID_ * HID_];
__device__ __half g_qh  [(size_t)MROWS * HID_];
__device__ __half g_kvh [(size_t)MROWS * 2 * NKV * HD_];  // [row, 512]: k@g*128, v@256+g*128
__device__ __half g_yh  [(size_t)MROWS * HID_];

// ---------------------------------------------------------------------------
// Helpers
// ---------------------------------------------------------------------------
__device__ __forceinline__ uint32_t packh2(float lo, float hi) {
    __half2 h = __floats2half2_rn(lo, hi);
    return *(uint32_t*)&h;
}

__device__ __forceinline__ void mma_f16(float c[4],
                                        uint32_t a0, uint32_t a1, uint32_t a2, uint32_t a3,
                                        uint32_t b0, uint32_t b1) {
    asm volatile(
        "mma.sync.aligned.m16n8k16.row.col.f32.f16.f16.f32 "
        "{%0,%1,%2,%3}, {%4,%5,%6,%7}, {%8,%9}, {%0,%1,%2,%3};"
        : "+f"(c[0]), "+f"(c[1]), "+f"(c[2]), "+f"(c[3])
        : "r"(a0), "r"(a1), "r"(a2), "r"(a3), "r"(b0), "r"(b1));
}

#define LDMX4(r0, r1, r2, r3, addr)                                             \
    asm volatile("ldmatrix.sync.aligned.m8n8.x4.shared.b16 {%0,%1,%2,%3}, [%4];" \
                 : "=r"(r0), "=r"(r1), "=r"(r2), "=r"(r3) : "r"(addr))

#define LDMX4T(r0, r1, r2, r3, addr)                                                  \
    asm volatile("ldmatrix.sync.aligned.m8n8.x4.trans.shared.b16 {%0,%1,%2,%3}, [%4];" \
                 : "=r"(r0), "=r"(r1), "=r"(r2), "=r"(r3) : "r"(addr))

#define CPA16(dst, src) \
    asm volatile("cp.async.cg.shared.global [%0], [%1], 16;" :: "r"(dst), "l"(src))
#define CP_COMMIT() asm volatile("cp.async.commit_group;" ::: "memory")
#define CP_WAIT(n)  asm volatile("cp.async.wait_group %0;" :: "n"(n) : "memory")

// ---------------------------------------------------------------------------
// Fused fp32 -> fp16 convert for all 5 buffers (one launch).
// ---------------------------------------------------------------------------
#define C_X  (MROWS * HID_ / 4)                  // 4194304
#define C_WQ (HID_ * HID_ / 4)                   // 1048576
#define C_WK (NKV * HD_ * HID_ / 4)              // 131072
#define C_TOT (C_X + 2 * C_WQ + 2 * C_WK)        // 6553600

__global__ __launch_bounds__(256) void cvt_all(const float* __restrict__ x,
                                               const float* __restrict__ Wq,
                                               const float* __restrict__ Wk,
                                               const float* __restrict__ Wv,
                                               const float* __restrict__ Wo,
                                               __half* __restrict__ xh,
                                               __half* __restrict__ wqh,
                                               __half* __restrict__ wkvh,
                                               __half* __restrict__ woh) {
    int i = blockIdx.x * 256 + threadIdx.x;
    const float* src;
    __half* dst;
    int off;
    if (i < C_X)                        { src = x;  dst = xh;  off = i; }
    else if ((i -= C_X) < C_WQ)         { src = Wq; dst = wqh; off = i; }
    else if ((i -= C_WQ) < C_WK)        { src = Wk; dst = wkvh; off = i; }
    else if ((i -= C_WK) < C_WK)        { src = Wv; dst = wkvh + (size_t)NKV * HD_ * HID_; off = i; }
    else if ((i -= C_WK) < C_WQ)        { src = Wo; dst = woh; off = i; }
    else return;
    float4 v = ((const float4*)src)[off];
    uint2 o = {packh2(v.x, v.y), packh2(v.z, v.w)};
    ((uint2*)dst)[off] = o;
}

// ---------------------------------------------------------------------------
// FP16 GEMM (NT) with 3-stage cp.async pipeline (R9 config — best measured).
// C[M,N] = A[M,K] * B[N,K]^T, fp16 in, fp16 or fp32 out (fp32 accumulate).
// 128x128x64 block tile, 256 threads = 8 warps, warp tile 64x32.
// ---------------------------------------------------------------------------
#define GST 36
#define STG_W (128 * GST)
#define STAGE_BYTES (2 * STG_W * 4)
#define GSMEM (3 * STAGE_BYTES)      // 110592

__global__ __launch_bounds__(256) void f16_gemm_pipe(const __half* __restrict__ A,
                                                     const __half* __restrict__ Bw,
                                                     void* __restrict__ Cout,
                                                     int M, int N, int K, int out_half) {
    extern __shared__ uint32_t su[];
    const uint32_t sbase = (uint32_t)__cvta_generic_to_shared(su);

    const int tid  = threadIdx.x;
    const int lane = tid & 31, warp = tid >> 5;
    const int gid  = lane >> 2, tig = lane & 3;
    const int wm   = (warp >> 2) * 64;
    const int wn   = (warp & 3) * 32;
    const int bm   = blockIdx.y * 128;
    const int bn   = blockIdx.x * 128;

    const int a_row = (lane & 7) + ((lane >> 3) & 1) * 8;
    const int a_cw  = (lane >> 4) * 4;
    const int b_row = (lane & 7) + (lane >> 4) * 8;
    const int b_cw  = ((lane >> 3) & 1) * 4;

    const int S = K >> 6;

    auto issue = [&](int s, int buf) {
        const int k0 = s << 6;
        const uint32_t abase = sbase + buf * STAGE_BYTES;
        const uint32_t bbase = abase + STG_W * 4;
#pragma unroll
        for (int i = 0; i < 4; i++) {
            int idx = i * 256 + tid;
            int r = idx >> 3, cq = idx & 7;
            CPA16(abase + (r * GST + cq * 4) * 4,
                  A + (size_t)(bm + r) * K + k0 + cq * 8);
        }
#pragma unroll
        for (int i = 0; i < 4; i++) {
            int idx = i * 256 + tid;
            int r = idx >> 3, cq = idx & 7;
            CPA16(bbase + (r * GST + cq * 4) * 4,
                  Bw + (size_t)(bn + r) * K + k0 + cq * 8);
        }
        CP_COMMIT();
    };

    float acc[4][4][4] = {};

    issue(0, 0);
    issue(1, 1);

    for (int s = 0; s < S; s++) {
        CP_WAIT(1);
        __syncthreads();
        if (s + 2 < S) issue(s + 2, (s + 2) % 3);

        const uint32_t abase = sbase + (s % 3) * STAGE_BYTES;
        const uint32_t bbase = abase + STG_W * 4;
#pragma unroll
        for (int kk = 0; kk < 4; kk++) {
            uint32_t af[4][4], bf[4][2];
#pragma unroll
            for (int mi = 0; mi < 4; mi++) {
                uint32_t addr = abase + (((wm + mi * 16 + a_row) * GST + kk * 8 + a_cw) << 2);
                LDMX4(af[mi][0], af[mi][1], af[mi][2], af[mi][3], addr);
            }
#pragma unroll
            for (int nb = 0; nb < 2; nb++) {
                uint32_t addr = bbase + (((wn + nb * 16 + b_row) * GST + kk * 8 + b_cw) << 2);
                LDMX4(bf[2 * nb][0], bf[2 * nb][1], bf[2 * nb + 1][0], bf[2 * nb + 1][1], addr);
            }
#pragma unroll
            for (int mi = 0; mi < 4; mi++)
#pragma unroll
                for (int ni = 0; ni < 4; ni++)
                    mma_f16(acc[mi][ni], af[mi][0], af[mi][1], af[mi][2], af[mi][3],
                            bf[ni][0], bf[ni][1]);
        }
    }

#pragma unroll
    for (int mi = 0; mi < 4; mi++)
#pragma unroll
        for (int ni = 0; ni < 4; ni++) {
            int row = bm + wm + mi * 16 + gid;
            int col = bn + wn + ni * 8 + 2 * tig;
            if (out_half) {
                __half* Ch = (__half*)Cout;
                *(uint32_t*)(Ch + (size_t)row * N + col) =
                    packh2(acc[mi][ni][0], acc[mi][ni][1]);
                *(uint32_t*)(Ch + (size_t)(row + 8) * N + col) =
                    packh2(acc[mi][ni][2], acc[mi][ni][3]);
            } else {
                float* Cf = (float*)Cout;
                float2 lo = {acc[mi][ni][0], acc[mi][ni][1]};
                float2 hi = {acc[mi][ni][2], acc[mi][ni][3]};
                *(float2*)(Cf + (size_t)row * N + col)       = lo;
                *(float2*)(Cf + (size_t)(row + 8) * N + col) = hi;
            }
        }
}

// ---------------------------------------------------------------------------
// Fused RoPE + RMSNorm on fp16 (fp32 math). One warp per 128-elem head row.
// ---------------------------------------------------------------------------
__global__ __launch_bounds__(256) void rope_rms_h(__half* __restrict__ q,
                                                  __half* __restrict__ kv,
                                                  const float* __restrict__ cosp,
                                                  const float* __restrict__ sinp) {
    int gw   = (blockIdx.x * 256 + threadIdx.x) >> 5;
    int lane = threadIdx.x & 31;
    const int QROWS = MROWS * NH;
    const int KROWS = MROWS * NKV;

    __half* hp;
    int t;
    if (gw < QROWS) {
        t = (gw >> 4) & (T_ - 1);
        hp = q + (size_t)gw * HD_;
    } else {
        int r = gw - QROWS;
        if (r >= KROWS) return;
        t = (r >> 1) & (T_ - 1);
        hp = kv + (size_t)(r >> 1) * 512 + (r & 1) * 128;
    }
    uint32_t* ptr = (uint32_t*)hp;

    float2 x0 = __half22float2(*(__half2*)&ptr[lane]);
    float2 x1 = __half22float2(*(__half2*)&ptr[lane + 32]);
    float c0  = cosp[t * 64 + lane],      sn0 = sinp[t * 64 + lane];
    float c1  = cosp[t * 64 + lane + 32], sn1 = sinp[t * 64 + lane + 32];

    float o0r = x0.x * c0 - x0.y * sn0;
    float o0i = x0.x * sn0 + x0.y * c0;
    float o1r = x1.x * c1 - x1.y * sn1;
    float o1i = x1.x * sn1 + x1.y * c1;

    float ss = o0r * o0r + o0i * o0i + o1r * o1r + o1i * o1i;
#pragma unroll
    for (int off = 16; off > 0; off >>= 1)
        ss += __shfl_xor_sync(0xffffffffu, ss, off);
    float sc = rsqrtf(ss * (1.0f / 128.0f) + 1.1920929e-7f);

    ptr[lane]      = packh2(o0r * sc, o0i * sc);
    ptr[lane + 32] = packh2(o1r * sc, o1i * sc);
}

// ---------------------------------------------------------------------------
// FP16 flash attention (causal, GQA 8:1), 128 q x 128 kv tiles.
// LPT scheduling: bx reversed so longest CTAs (most kv tiles) launch first.
// ---------------------------------------------------------------------------
#define FH    68
#define OFF_K0 (128 * FH)
#define KVBUF  (2 * 128 * FH)
#define FLASH_SMEM_BYTES ((OFF_K0 + 2 * KVBUF) * 4)   // 174080

__global__ __launch_bounds__(256) void flash_h(const __half* __restrict__ Q,
                                               const __half* __restrict__ KV,
                                               __half* __restrict__ Y) {
    extern __shared__ uint32_t su[];
    const uint32_t qs_b = (uint32_t)__cvta_generic_to_shared(su);

    const int bx = gridDim.x - 1 - blockIdx.x;   // LPT: longest work first
    const int h = blockIdx.y, b = blockIdx.z;
    const int g = h >> 3;
    const int tid = threadIdx.x, warp = tid >> 5, lane = tid & 31;
    const int gid = lane >> 2, tig = lane & 3;
    const int q0 = bx * 128;
    const int w16 = warp * 16;
    const float scale = 0.08838834764831845f;

    const int a_row = (lane & 7) + ((lane >> 3) & 1) * 8;
    const int a_cw  = (lane >> 4) * 4;
    const int kb_row = (lane & 7) + (lane >> 4) * 8;
    const int kb_cw  = ((lane >> 3) & 1) * 4;
    const int vb_row = (lane & 7) + ((lane >> 3) & 1) * 8;
    const int vb_cw  = (lane >> 4) * 4;

    const int nkv = bx + 1;

    auto issue_kv = [&](int kt, int buf) {
        const uint32_t kbase = qs_b + (OFF_K0 + buf * KVBUF) * 4;
        const uint32_t vbase = kbase + 128 * FH * 4;
#pragma unroll
        for (int i = 0; i < 8; i++) {
            int idx = i * 256 + tid;
            int row = idx >> 4, cq = idx & 15;
            size_t base = (size_t)(b * T_ + kt * 128 + row) * 512 + g * 128 + cq * 8;
            CPA16(kbase + (row * FH + cq * 4) * 4, KV + base);
            CPA16(vbase + (row * FH + cq * 4) * 4, KV + base + 256);
        }
        CP_COMMIT();
    };

    issue_kv(0, 0);

#pragma unroll
    for (int i = 0; i < 8; i++) {
        int idx = i * 256 + tid;
        int row = idx >> 4, cq = idx & 15;
        *(uint4*)&su[row * FH + cq * 4] =
            *(const uint4*)(Q + ((size_t)((b * T_ + q0 + row) * NH + h)) * HD_ + cq * 8);
    }

    float m0 = -INFINITY, m1 = -INFINITY, l0 = 0.0f, l1 = 0.0f;
    float O[16][4];
#pragma unroll
    for (int ni = 0; ni < 16; ni++)
        O[ni][0] = O[ni][1] = O[ni][2] = O[ni][3] = 0.0f;

    for (int kt = 0; kt < nkv; kt++) {
        const int buf = kt & 1;
        CP_WAIT(0);
        __syncthreads();
        if (kt + 1 < nkv) issue_kv(kt + 1, buf ^ 1);

        const uint32_t ks_b = qs_b + (OFF_K0 + buf * KVBUF) * 4;
        const uint32_t vs_b = ks_b + 128 * FH * 4;

        float s[16][4] = {};
#pragma unroll
        for (int kk = 0; kk < 8; kk++) {
            uint32_t a0, a1, a2, a3;
            LDMX4(a0, a1, a2, a3, qs_b + (((w16 + a_row) * FH + kk * 8 + a_cw) << 2));
#pragma unroll
            for (int nb = 0; nb < 8; nb++) {
                uint32_t b0, b1, b2, b3;
                LDMX4(b0, b1, b2, b3,
                      ks_b + (((nb * 16 + kb_row) * FH + kk * 8 + kb_cw) << 2));
                mma_f16(s[2 * nb],     a0, a1, a2, a3, b0, b1);
                mma_f16(s[2 * nb + 1], a0, a1, a2, a3, b2, b3);
            }
        }
#pragma unroll
        for (int ni = 0; ni < 16; ni++) {
            s[ni][0] *= scale; s[ni][1] *= scale;
            s[ni][2] *= scale; s[ni][3] *= scale;
        }

        if (kt == bx) {
            int r_lo = w16 + gid, r_hi = r_lo + 8;
#pragma unroll
            for (int ni = 0; ni < 16; ni++) {
                int col = ni * 8 + 2 * tig;
                if (col     > r_lo) s[ni][0] = -INFINITY;
                if (col + 1 > r_lo) s[ni][1] = -INFINITY;
                if (col     > r_hi) s[ni][2] = -INFINITY;
                if (col + 1 > r_hi) s[ni][3] = -INFINITY;
            }
        }

        float mx0 = -INFINITY, mx1 = -INFINITY;
#pragma unroll
        for (int ni = 0; ni < 16; ni++) {
            mx0 = fmaxf(mx0, fmaxf(s[ni][0], s[ni][1]));
            mx1 = fmaxf(mx1, fmaxf(s[ni][2], s[ni][3]));
        }
        mx0 = fmaxf(mx0, __shfl_xor_sync(0xffffffffu, mx0, 1));
        mx0 = fmaxf(mx0, __shfl_xor_sync(0xffffffffu, mx0, 2));
        mx1 = fmaxf(mx1, __shfl_xor_sync(0xffffffffu, mx1, 1));
        mx1 = fmaxf(mx1, __shfl_xor_sync(0xffffffffu, mx1, 2));

        float mn0 = fmaxf(m0, mx0), mn1 = fmaxf(m1, mx1);
        float al0 = __expf(m0 - mn0), al1 = __expf(m1 - mn1);
        m0 = mn0; m1 = mn1;

        float ps0 = 0.0f, ps1 = 0.0f;
#pragma unroll
        for (int ni = 0; ni < 16; ni++) {
            s[ni][0] = __expf(s[ni][0] - mn0);
            s[ni][1] = __expf(s[ni][1] - mn0);
            s[ni][2] = __expf(s[ni][2] - mn1);
            s[ni][3] = __expf(s[ni][3] - mn1);
            ps0 += s[ni][0] + s[ni][1];
            ps1 += s[ni][2] + s[ni][3];
        }
        ps0 += __shfl_xor_sync(0xffffffffu, ps0, 1);
        ps0 += __shfl_xor_sync(0xffffffffu, ps0, 2);
        ps1 += __shfl_xor_sync(0xffffffffu, ps1, 1);
        ps1 += __shfl_xor_sync(0xffffffffu, ps1, 2);
        l0 = l0 * al0 + ps0;
        l1 = l1 * al1 + ps1;

#pragma unroll
        for (int ni = 0; ni < 16; ni++) {
            O[ni][0] *= al0; O[ni][1] *= al0;
            O[ni][2] *= al1; O[ni][3] *= al1;
        }

#pragma unroll
        for (int j = 0; j < 8; j++) {
            uint32_t a0 = packh2(s[2 * j][0],     s[2 * j][1]);
            uint32_t a1 = packh2(s[2 * j][2],     s[2 * j][3]);
            uint32_t a2 = packh2(s[2 * j + 1][0], s[2 * j + 1][1]);
            uint32_t a3 = packh2(s[2 * j + 1][2], s[2 * j + 1][3]);
#pragma unroll
            for (int nb = 0; nb < 8; nb++) {
                uint32_t b0, b1, b2, b3;
                LDMX4T(b0, b1, b2, b3,
                       vs_b + (((j * 16 + vb_row) * FH + nb * 8 + vb_cw) << 2));
                mma_f16(O[2 * nb],     a0, a1, a2, a3, b0, b1);
                mma_f16(O[2 * nb + 1], a0, a1, a2, a3, b2, b3);
            }
        }
    }

    float inv0 = 1.0f / l0, inv1 = 1.0f / l1;
    int row0 = q0 + w16 + gid, row1 = row0 + 8;
#pragma unroll
    for (int ni = 0; ni < 16; ni++) {
        int col = ni * 8 + 2 * tig;
        *(uint32_t*)(Y + ((size_t)((b * T_ + row0) * NH + h)) * HD_ + col) =
            packh2(O[ni][0] * inv0, O[ni][1] * inv0);
        *(uint32_t*)(Y + ((size_t)((b * T_ + row1) * NH + h)) * HD_ + col) =
            packh2(O[ni][2] * inv1, O[ni][3] * inv1);
    }
}

// ---------------------------------------------------------------------------
// Launch
// ---------------------------------------------------------------------------
extern "C" void kernel_launch(void* const* d_in, const int* in_sizes, int n_in,
                              void* d_out, int out_size) {
    const float* x    = (const float*)d_in[0];
    const float* cosp = (const float*)d_in[1];
    const float* sinp = (const float*)d_in[2];
    const float* Wq   = (const float*)d_in[3];
    const float* Wk   = (const float*)d_in[4];
    const float* Wv   = (const float*)d_in[5];
    const float* Wo   = (const float*)d_in[6];
    float* out = (float*)d_out;

    __half *xh, *wqh, *wkvh, *woh, *qh, *kvh, *yh;
    cudaGetSymbolAddress((void**)&xh,   g_xh);
    cudaGetSymbolAddress((void**)&wqh,  g_wqh);
    cudaGetSymbolAddress((void**)&wkvh, g_wkvh);
    cudaGetSymbolAddress((void**)&woh,  g_woh);
    cudaGetSymbolAddress((void**)&qh,   g_qh);
    cudaGetSymbolAddress((void**)&kvh,  g_kvh);
    cudaGetSymbolAddress((void**)&yh,   g_yh);

    cudaFuncSetAttribute(f16_gemm_pipe, cudaFuncAttributeMaxDynamicSharedMemorySize, GSMEM);
    cudaFuncSetAttribute(flash_h, cudaFuncAttributeMaxDynamicSharedMemorySize,
                         FLASH_SMEM_BYTES);

    dim3 blk(256);
    const int KVN = 2 * NKV * HD_;   // 512
    // One fused fp32 -> fp16 convert for x + all weights
    cvt_all<<<(C_TOT + 255) / 256, blk>>>(x, Wq, Wk, Wv, Wo, xh, wqh, wkvh, woh);

    // Projections (fp16 mma.sync, 128x128 tiles, cp.async pipelined)
    f16_gemm_pipe<<<dim3(HID_ / 128, MROWS / 128), blk, GSMEM>>>(xh, wqh, qh, MROWS, HID_, HID_, 1);
    f16_gemm_pipe<<<dim3(KVN / 128, MROWS / 128), blk, GSMEM>>>(xh, wkvh, kvh, MROWS, KVN, HID_, 1);
    // RoPE + RMSNorm (fp16 in/out, fp32 math)
    rope_rms_h<<<(MROWS * (NH + NKV)) / 8, blk>>>(qh, kvh, cosp, sinp);
    // Flash attention (fp16 mma.sync, BKV=128, LPT-ordered, cp.async KV)
    flash_h<<<dim3(T_ / 128, NH, B_), blk, FLASH_SMEM_BYTES>>>(qh, kvh, yh);
    // Output projection -> fp32 out
    f16_gemm_pipe<<<dim3(HID_ / 128, MROWS / 128), blk, GSMEM>>>(yh, woh, out, MROWS, HID_, HID_, 0);
}

// round 16
// speedup vs baseline: 1.0732x; 1.0031x over previous
#include <cuda_runtime.h>
#include <cuda_fp16.h>
#include <math.h>
#include <stdint.h>

// Problem constants
#define B_    4
#define T_    2048
#define HID_  2048
#define NH    16
#define NKV   2
#define HD_   128
#define MROWS (B_ * T_)   // 8192

// fp16 scratch (allocation-free rule: __device__ globals)
__device__ __half g_xh  [(size_t)MROWS * HID_];
__device__ __half g_wqh [(size_t)HID_ * HID_];
__device__ __half g_wkvh[(size_t)2 * NKV * HD_ * HID_];   // Wk rows 0-255, Wv rows 256-511
__device__ __half g_woh [(size_t)HID_ * HID_];
__device__ __half g_qh  [(size_t)MROWS * HID_];
__device__ __half g_kvh [(size_t)MROWS * 2 * NKV * HD_];  // [row, 512]: k@g*128, v@256+g*128
__device__ __half g_yh  [(size_t)MROWS * HID_];

// ---------------------------------------------------------------------------
// Helpers
// ---------------------------------------------------------------------------
__device__ __forceinline__ uint32_t packh2(float lo, float hi) {
    __half2 h = __floats2half2_rn(lo, hi);
    return *(uint32_t*)&h;
}

__device__ __forceinline__ void mma_f16(float c[4],
                                        uint32_t a0, uint32_t a1, uint32_t a2, uint32_t a3,
                                        uint32_t b0, uint32_t b1) {
    asm volatile(
        "mma.sync.aligned.m16n8k16.row.col.f32.f16.f16.f32 "
        "{%0,%1,%2,%3}, {%4,%5,%6,%7}, {%8,%9}, {%0,%1,%2,%3};"
        : "+f"(c[0]), "+f"(c[1]), "+f"(c[2]), "+f"(c[3])
        : "r"(a0), "r"(a1), "r"(a2), "r"(a3), "r"(b0), "r"(b1));
}

#define LDMX4(r0, r1, r2, r3, addr)                                             \
    asm volatile("ldmatrix.sync.aligned.m8n8.x4.shared.b16 {%0,%1,%2,%3}, [%4];" \
                 : "=r"(r0), "=r"(r1), "=r"(r2), "=r"(r3) : "r"(addr))

#define LDMX4T(r0, r1, r2, r3, addr)                                                  \
    asm volatile("ldmatrix.sync.aligned.m8n8.x4.trans.shared.b16 {%0,%1,%2,%3}, [%4];" \
                 : "=r"(r0), "=r"(r1), "=r"(r2), "=r"(r3) : "r"(addr))

#define CPA16(dst, src) \
    asm volatile("cp.async.cg.shared.global [%0], [%1], 16;" :: "r"(dst), "l"(src))
#define CP_COMMIT() asm volatile("cp.async.commit_group;" ::: "memory")
#define CP_WAIT(n)  asm volatile("cp.async.wait_group %0;" :: "n"(n) : "memory")

// ---------------------------------------------------------------------------
// Fused fp32 -> fp16 convert for all 5 buffers (one launch).
// ---------------------------------------------------------------------------
#define C_X  (MROWS * HID_ / 4)                  // 4194304
#define C_WQ (HID_ * HID_ / 4)                   // 1048576
#define C_WK (NKV * HD_ * HID_ / 4)              // 131072
#define C_TOT (C_X + 2 * C_WQ + 2 * C_WK)        // 6553600

__global__ __launch_bounds__(256) void cvt_all(const float* __restrict__ x,
                                               const float* __restrict__ Wq,
                                               const float* __restrict__ Wk,
                                               const float* __restrict__ Wv,
                                               const float* __restrict__ Wo,
                                               __half* __restrict__ xh,
                                               __half* __restrict__ wqh,
                                               __half* __restrict__ wkvh,
                                               __half* __restrict__ woh) {
    int i = blockIdx.x * 256 + threadIdx.x;
    const float* src;
    __half* dst;
    int off;
    if (i < C_X)                        { src = x;  dst = xh;  off = i; }
    else if ((i -= C_X) < C_WQ)         { src = Wq; dst = wqh; off = i; }
    else if ((i -= C_WQ) < C_WK)        { src = Wk; dst = wkvh; off = i; }
    else if ((i -= C_WK) < C_WK)        { src = Wv; dst = wkvh + (size_t)NKV * HD_ * HID_; off = i; }
    else if ((i -= C_WK) < C_WQ)        { src = Wo; dst = woh; off = i; }
    else return;
    float4 v = ((const float4*)src)[off];
    uint2 o = {packh2(v.x, v.y), packh2(v.z, v.w)};
    ((uint2*)dst)[off] = o;
}

// ---------------------------------------------------------------------------
// Shared GEMM config (128x128x64 tile, 3-stage cp.async — best measured).
// ---------------------------------------------------------------------------
#define GST 36
#define STG_W (128 * GST)
#define STAGE_BYTES (2 * STG_W * 4)
#define GSMEM (3 * STAGE_BYTES)      // 110592

// ---------------------------------------------------------------------------
// Merged Q+KV projection with fused RoPE + RMSNorm epilogue.
// Grid (20, 64): bx<16 -> Q tile (head bx) into qh [row,2048];
//                bx>=16 -> KV tile into kvh [row,512] (bx-16<2: k -> rope+rms).
// A 128-col output tile == one head, so RoPE pairs (2i,2i+1) sit in one
// thread's C-fragment pair; RMSNorm row-sum via quad shuffle + smem reduce.
// ---------------------------------------------------------------------------
__global__ __launch_bounds__(256) void proj_fused(const __half* __restrict__ A,
                                                  const __half* __restrict__ WqH,
                                                  const __half* __restrict__ WkvH,
                                                  __half* __restrict__ qh,
                                                  __half* __restrict__ kvh,
                                                  const float* __restrict__ cosp,
                                                  const float* __restrict__ sinp) {
    extern __shared__ uint32_t su[];
    const uint32_t sbase = (uint32_t)__cvta_generic_to_shared(su);

    const int tid  = threadIdx.x;
    const int lane = tid & 31, warp = tid >> 5;
    const int gid  = lane >> 2, tig = lane & 3;
    const int wm   = (warp >> 2) * 64;
    const int wn   = (warp & 3) * 32;
    const int bm   = blockIdx.y * 128;
    const int bx   = blockIdx.x;

    const __half* Bw;
    __half* Cout;
    int bn, Nout, rope;
    if (bx < 16) { Bw = WqH;  bn = bx * 128;        Cout = qh;  Nout = HID_; rope = 1; }
    else         { Bw = WkvH; bn = (bx - 16) * 128; Cout = kvh; Nout = 512;  rope = (bx < 18); }

    const int a_row = (lane & 7) + ((lane >> 3) & 1) * 8;
    const int a_cw  = (lane >> 4) * 4;
    const int b_row = (lane & 7) + (lane >> 4) * 8;
    const int b_cw  = ((lane >> 3) & 1) * 4;

    const int K = HID_, S = K >> 6;

    auto issue = [&](int s, int buf) {
        const int k0 = s << 6;
        const uint32_t abase = sbase + buf * STAGE_BYTES;
        const uint32_t bbase = abase + STG_W * 4;
#pragma unroll
        for (int i = 0; i < 4; i++) {
            int idx = i * 256 + tid;
            int r = idx >> 3, cq = idx & 7;
            CPA16(abase + (r * GST + cq * 4) * 4,
                  A + (size_t)(bm + r) * K + k0 + cq * 8);
        }
#pragma unroll
        for (int i = 0; i < 4; i++) {
            int idx = i * 256 + tid;
            int r = idx >> 3, cq = idx & 7;
            CPA16(bbase + (r * GST + cq * 4) * 4,
                  Bw + (size_t)(bn + r) * K + k0 + cq * 8);
        }
        CP_COMMIT();
    };

    float acc[4][4][4] = {};

    issue(0, 0);
    issue(1, 1);

    for (int s = 0; s < S; s++) {
        CP_WAIT(1);
        __syncthreads();
        if (s + 2 < S) issue(s + 2, (s + 2) % 3);

        const uint32_t abase = sbase + (s % 3) * STAGE_BYTES;
        const uint32_t bbase = abase + STG_W * 4;
#pragma unroll
        for (int kk = 0; kk < 4; kk++) {
            uint32_t af[4][4], bf[4][2];
#pragma unroll
            for (int mi = 0; mi < 4; mi++) {
                uint32_t addr = abase + (((wm + mi * 16 + a_row) * GST + kk * 8 + a_cw) << 2);
                LDMX4(af[mi][0], af[mi][1], af[mi][2], af[mi][3], addr);
            }
#pragma unroll
            for (int nb = 0; nb < 2; nb++) {
                uint32_t addr = bbase + (((wn + nb * 16 + b_row) * GST + kk * 8 + b_cw) << 2);
                LDMX4(bf[2 * nb][0], bf[2 * nb][1], bf[2 * nb + 1][0], bf[2 * nb + 1][1], addr);
            }
#pragma unroll
            for (int mi = 0; mi < 4; mi++)
#pragma unroll
                for (int ni = 0; ni < 4; ni++)
                    mma_f16(acc[mi][ni], af[mi][0], af[mi][1], af[mi][2], af[mi][3],
                            bf[ni][0], bf[ni][1]);
        }
    }

    if (rope) {
        // --- RoPE on register fragments + per-row sum of squares ---
        float ss0[4], ss1[4];
#pragma unroll
        for (int mi = 0; mi < 4; mi++) {
            ss0[mi] = 0.0f; ss1[mi] = 0.0f;
            int t0 = (bm + wm + mi * 16 + gid) & (T_ - 1);
            int t1 = t0 + 8;
#pragma unroll
            for (int ni = 0; ni < 4; ni++) {
                int i = (wn >> 1) + ni * 4 + tig;   // pair index within head
                float c0 = cosp[t0 * 64 + i], s0 = sinp[t0 * 64 + i];
                float c1 = cosp[t1 * 64 + i], s1 = sinp[t1 * 64 + i];
                float xr = acc[mi][ni][0], xi = acc[mi][ni][1];
                acc[mi][ni][0] = xr * c0 - xi * s0;
                acc[mi][ni][1] = xr * s0 + xi * c0;
                ss0[mi] += acc[mi][ni][0] * acc[mi][ni][0] + acc[mi][ni][1] * acc[mi][ni][1];
                xr = acc[mi][ni][2]; xi = acc[mi][ni][3];
                acc[mi][ni][2] = xr * c1 - xi * s1;
                acc[mi][ni][3] = xr * s1 + xi * c1;
                ss1[mi] += acc[mi][ni][2] * acc[mi][ni][2] + acc[mi][ni][3] * acc[mi][ni][3];
            }
            ss0[mi] += __shfl_xor_sync(0xffffffffu, ss0[mi], 1);
            ss0[mi] += __shfl_xor_sync(0xffffffffu, ss0[mi], 2);
            ss1[mi] += __shfl_xor_sync(0xffffffffu, ss1[mi], 1);
            ss1[mi] += __shfl_xor_sync(0xffffffffu, ss1[mi], 2);
        }
        // --- cross-warp (4 col-groups) reduction via smem (pipeline smem idle) ---
        float* red = (float*)su;                 // [128 rows][4 col-groups]
        __syncthreads();
        if (tig == 0) {
#pragma unroll
            for (int mi = 0; mi < 4; mi++) {
                red[(wm + mi * 16 + gid) * 4 + (wn >> 5)]     = ss0[mi];
                red[(wm + mi * 16 + gid + 8) * 4 + (wn >> 5)] = ss1[mi];
            }
        }
        __syncthreads();
#pragma unroll
        for (int mi = 0; mi < 4; mi++) {
            int r0 = (wm + mi * 16 + gid) * 4, r1 = r0 + 32;
            float v0 = red[r0] + red[r0 + 1] + red[r0 + 2] + red[r0 + 3];
            float v1 = red[r1] + red[r1 + 1] + red[r1 + 2] + red[r1 + 3];
            float sc0 = rsqrtf(v0 * (1.0f / 128.0f) + 1.1920929e-7f);
            float sc1 = rsqrtf(v1 * (1.0f / 128.0f) + 1.1920929e-7f);
#pragma unroll
            for (int ni = 0; ni < 4; ni++) {
                acc[mi][ni][0] *= sc0; acc[mi][ni][1] *= sc0;
                acc[mi][ni][2] *= sc1; acc[mi][ni][3] *= sc1;
            }
        }
    }

#pragma unroll
    for (int mi = 0; mi < 4; mi++)
#pragma unroll
        for (int ni = 0; ni < 4; ni++) {
            int row = bm + wm + mi * 16 + gid;
            int col = bn + wn + ni * 8 + 2 * tig;
            *(uint32_t*)(Cout + (size_t)row * Nout + col) =
                packh2(acc[mi][ni][0], acc[mi][ni][1]);
            *(uint32_t*)(Cout + (size_t)(row + 8) * Nout + col) =
                packh2(acc[mi][ni][2], acc[mi][ni][3]);
        }
}

// ---------------------------------------------------------------------------
// Plain FP16 GEMM (NT) for Wo, fp32 out. (R9 config)
// ---------------------------------------------------------------------------
__global__ __launch_bounds__(256) void f16_gemm_pipe(const __half* __restrict__ A,
                                                     const __half* __restrict__ Bw,
                                                     float* __restrict__ Cf,
                                                     int M, int N, int K) {
    extern __shared__ uint32_t su[];
    const uint32_t sbase = (uint32_t)__cvta_generic_to_shared(su);

    const int tid  = threadIdx.x;
    const int lane = tid & 31, warp = tid >> 5;
    const int gid  = lane >> 2, tig = lane & 3;
    const int wm   = (warp >> 2) * 64;
    const int wn   = (warp & 3) * 32;
    const int bm   = blockIdx.y * 128;
    const int bn   = blockIdx.x * 128;

    const int a_row = (lane & 7) + ((lane >> 3) & 1) * 8;
    const int a_cw  = (lane >> 4) * 4;
    const int b_row = (lane & 7) + (lane >> 4) * 8;
    const int b_cw  = ((lane >> 3) & 1) * 4;

    const int S = K >> 6;

    auto issue = [&](int s, int buf) {
        const int k0 = s << 6;
        const uint32_t abase = sbase + buf * STAGE_BYTES;
        const uint32_t bbase = abase + STG_W * 4;
#pragma unroll
        for (int i = 0; i < 4; i++) {
            int idx = i * 256 + tid;
            int r = idx >> 3, cq = idx & 7;
            CPA16(abase + (r * GST + cq * 4) * 4,
                  A + (size_t)(bm + r) * K + k0 + cq * 8);
        }
#pragma unroll
        for (int i = 0; i < 4; i++) {
            int idx = i * 256 + tid;
            int r = idx >> 3, cq = idx & 7;
            CPA16(bbase + (r * GST + cq * 4) * 4,
                  Bw + (size_t)(bn + r) * K + k0 + cq * 8);
        }
        CP_COMMIT();
    };

    float acc[4][4][4] = {};

    issue(0, 0);
    issue(1, 1);

    for (int s = 0; s < S; s++) {
        CP_WAIT(1);
        __syncthreads();
        if (s + 2 < S) issue(s + 2, (s + 2) % 3);

        const uint32_t abase = sbase + (s % 3) * STAGE_BYTES;
        const uint32_t bbase = abase + STG_W * 4;
#pragma unroll
        for (int kk = 0; kk < 4; kk++) {
            uint32_t af[4][4], bf[4][2];
#pragma unroll
            for (int mi = 0; mi < 4; mi++) {
                uint32_t addr = abase + (((wm + mi * 16 + a_row) * GST + kk * 8 + a_cw) << 2);
                LDMX4(af[mi][0], af[mi][1], af[mi][2], af[mi][3], addr);
            }
#pragma unroll
            for (int nb = 0; nb < 2; nb++) {
                uint32_t addr = bbase + (((wn + nb * 16 + b_row) * GST + kk * 8 + b_cw) << 2);
                LDMX4(bf[2 * nb][0], bf[2 * nb][1], bf[2 * nb + 1][0], bf[2 * nb + 1][1], addr);
            }
#pragma unroll
            for (int mi = 0; mi < 4; mi++)
#pragma unroll
                for (int ni = 0; ni < 4; ni++)
                    mma_f16(acc[mi][ni], af[mi][0], af[mi][1], af[mi][2], af[mi][3],
                            bf[ni][0], bf[ni][1]);
        }
    }

#pragma unroll
    for (int mi = 0; mi < 4; mi++)
#pragma unroll
        for (int ni = 0; ni < 4; ni++) {
            int row = bm + wm + mi * 16 + gid;
            int col = bn + wn + ni * 8 + 2 * tig;
            float2 lo = {acc[mi][ni][0], acc[mi][ni][1]};
            float2 hi = {acc[mi][ni][2], acc[mi][ni][3]};
            *(float2*)(Cf + (size_t)row * N + col)       = lo;
            *(float2*)(Cf + (size_t)(row + 8) * N + col) = hi;
        }
}

// ---------------------------------------------------------------------------
// FP16 flash attention (causal, GQA 8:1), 128 q x 128 kv tiles, LPT order.
// ---------------------------------------------------------------------------
#define FH    68
#define OFF_K0 (128 * FH)
#define KVBUF  (2 * 128 * FH)
#define FLASH_SMEM_BYTES ((OFF_K0 + 2 * KVBUF) * 4)   // 174080

__global__ __launch_bounds__(256) void flash_h(const __half* __restrict__ Q,
                                               const __half* __restrict__ KV,
                                               __half* __restrict__ Y) {
    extern __shared__ uint32_t su[];
    const uint32_t qs_b = (uint32_t)__cvta_generic_to_shared(su);

    const int bx = gridDim.x - 1 - blockIdx.x;   // LPT: longest work first
    const int h = blockIdx.y, b = blockIdx.z;
    const int g = h >> 3;
    const int tid = threadIdx.x, warp = tid >> 5, lane = tid & 31;
    const int gid = lane >> 2, tig = lane & 3;
    const int q0 = bx * 128;
    const int w16 = warp * 16;
    const float scale = 0.08838834764831845f;

    const int a_row = (lane & 7) + ((lane >> 3) & 1) * 8;
    const int a_cw  = (lane >> 4) * 4;
    const int kb_row = (lane & 7) + (lane >> 4) * 8;
    const int kb_cw  = ((lane >> 3) & 1) * 4;
    const int vb_row = (lane & 7) + ((lane >> 3) & 1) * 8;
    const int vb_cw  = (lane >> 4) * 4;

    const int nkv = bx + 1;

    auto issue_kv = [&](int kt, int buf) {
        const uint32_t kbase = qs_b + (OFF_K0 + buf * KVBUF) * 4;
        const uint32_t vbase = kbase + 128 * FH * 4;
#pragma unroll
        for (int i = 0; i < 8; i++) {
            int idx = i * 256 + tid;
            int row = idx >> 4, cq = idx & 15;
            size_t base = (size_t)(b * T_ + kt * 128 + row) * 512 + g * 128 + cq * 8;
            CPA16(kbase + (row * FH + cq * 4) * 4, KV + base);
            CPA16(vbase + (row * FH + cq * 4) * 4, KV + base + 256);
        }
        CP_COMMIT();
    };

    issue_kv(0, 0);

#pragma unroll
    for (int i = 0; i < 8; i++) {
        int idx = i * 256 + tid;
        int row = idx >> 4, cq = idx & 15;
        *(uint4*)&su[row * FH + cq * 4] =
            *(const uint4*)(Q + ((size_t)((b * T_ + q0 + row) * NH + h)) * HD_ + cq * 8);
    }

    float m0 = -INFINITY, m1 = -INFINITY, l0 = 0.0f, l1 = 0.0f;
    float O[16][4];
#pragma unroll
    for (int ni = 0; ni < 16; ni++)
        O[ni][0] = O[ni][1] = O[ni][2] = O[ni][3] = 0.0f;

    for (int kt = 0; kt < nkv; kt++) {
        const int buf = kt & 1;
        CP_WAIT(0);
        __syncthreads();
        if (kt + 1 < nkv) issue_kv(kt + 1, buf ^ 1);

        const uint32_t ks_b = qs_b + (OFF_K0 + buf * KVBUF) * 4;
        const uint32_t vs_b = ks_b + 128 * FH * 4;

        float s[16][4] = {};
#pragma unroll
        for (int kk = 0; kk < 8; kk++) {
            uint32_t a0, a1, a2, a3;
            LDMX4(a0, a1, a2, a3, qs_b + (((w16 + a_row) * FH + kk * 8 + a_cw) << 2));
#pragma unroll
            for (int nb = 0; nb < 8; nb++) {
                uint32_t b0, b1, b2, b3;
                LDMX4(b0, b1, b2, b3,
                      ks_b + (((nb * 16 + kb_row) * FH + kk * 8 + kb_cw) << 2));
                mma_f16(s[2 * nb],     a0, a1, a2, a3, b0, b1);
                mma_f16(s[2 * nb + 1], a0, a1, a2, a3, b2, b3);
            }
        }
#pragma unroll
        for (int ni = 0; ni < 16; ni++) {
            s[ni][0] *= scale; s[ni][1] *= scale;
            s[ni][2] *= scale; s[ni][3] *= scale;
        }

        if (kt == bx) {
            int r_lo = w16 + gid, r_hi = r_lo + 8;
#pragma unroll
            for (int ni = 0; ni < 16; ni++) {
                int col = ni * 8 + 2 * tig;
                if (col     > r_lo) s[ni][0] = -INFINITY;
                if (col + 1 > r_lo) s[ni][1] = -INFINITY;
                if (col     > r_hi) s[ni][2] = -INFINITY;
                if (col + 1 > r_hi) s[ni][3] = -INFINITY;
            }
        }

        float mx0 = -INFINITY, mx1 = -INFINITY;
#pragma unroll
        for (int ni = 0; ni < 16; ni++) {
            mx0 = fmaxf(mx0, fmaxf(s[ni][0], s[ni][1]));
            mx1 = fmaxf(mx1, fmaxf(s[ni][2], s[ni][3]));
        }
        mx0 = fmaxf(mx0, __shfl_xor_sync(0xffffffffu, mx0, 1));
        mx0 = fmaxf(mx0, __shfl_xor_sync(0xffffffffu, mx0, 2));
        mx1 = fmaxf(mx1, __shfl_xor_sync(0xffffffffu, mx1, 1));
        mx1 = fmaxf(mx1, __shfl_xor_sync(0xffffffffu, mx1, 2));

        float mn0 = fmaxf(m0, mx0), mn1 = fmaxf(m1, mx1);
        float al0 = __expf(m0 - mn0), al1 = __expf(m1 - mn1);
        m0 = mn0; m1 = mn1;

        float ps0 = 0.0f, ps1 = 0.0f;
#pragma unroll
        for (int ni = 0; ni < 16; ni++) {
            s[ni][0] = __expf(s[ni][0] - mn0);
            s[ni][1] = __expf(s[ni][1] - mn0);
            s[ni][2] = __expf(s[ni][2] - mn1);
            s[ni][3] = __expf(s[ni][3] - mn1);
            ps0 += s[ni][0] + s[ni][1];
            ps1 += s[ni][2] + s[ni][3];
        }
        ps0 += __shfl_xor_sync(0xffffffffu, ps0, 1);
        ps0 += __shfl_xor_sync(0xffffffffu, ps0, 2);
        ps1 += __shfl_xor_sync(0xffffffffu, ps1, 1);
        ps1 += __shfl_xor_sync(0xffffffffu, ps1, 2);
        l0 = l0 * al0 + ps0;
        l1 = l1 * al1 + ps1;

#pragma unroll
        for (int ni = 0; ni < 16; ni++) {
            O[ni][0] *= al0; O[ni][1] *= al0;
            O[ni][2] *= al1; O[ni][3] *= al1;
        }

#pragma unroll
        for (int j = 0; j < 8; j++) {
            uint32_t a0 = packh2(s[2 * j][0],     s[2 * j][1]);
            uint32_t a1 = packh2(s[2 * j][2],     s[2 * j][3]);
            uint32_t a2 = packh2(s[2 * j + 1][0], s[2 * j + 1][1]);
            uint32_t a3 = packh2(s[2 * j + 1][2], s[2 * j + 1][3]);
#pragma unroll
            for (int nb = 0; nb < 8; nb++) {
                uint32_t b0, b1, b2, b3;
                LDMX4T(b0, b1, b2, b3,
                       vs_b + (((j * 16 + vb_row) * FH + nb * 8 + vb_cw) << 2));
                mma_f16(O[2 * nb],     a0, a1, a2, a3, b0, b1);
                mma_f16(O[2 * nb + 1], a0, a1, a2, a3, b2, b3);
            }
        }
    }

    float inv0 = 1.0f / l0, inv1 = 1.0f / l1;
    int row0 = q0 + w16 + gid, row1 = row0 + 8;
#pragma unroll
    for (int ni = 0; ni < 16; ni++) {
        int col = ni * 8 + 2 * tig;
        *(uint32_t*)(Y + ((size_t)((b * T_ + row0) * NH + h)) * HD_ + col) =
            packh2(O[ni][0] * inv0, O[ni][1] * inv0);
        *(uint32_t*)(Y + ((size_t)((b * T_ + row1) * NH + h)) * HD_ + col) =
            packh2(O[ni][2] * inv1, O[ni][3] * inv1);
    }
}

// ---------------------------------------------------------------------------
// Launch
// ---------------------------------------------------------------------------
extern "C" void kernel_launch(void* const* d_in, const int* in_sizes, int n_in,
                              void* d_out, int out_size) {
    const float* x    = (const float*)d_in[0];
    const float* cosp = (const float*)d_in[1];
    const float* sinp = (const float*)d_in[2];
    const float* Wq   = (const float*)d_in[3];
    const float* Wk   = (const float*)d_in[4];
    const float* Wv   = (const float*)d_in[5];
    const float* Wo   = (const float*)d_in[6];
    float* out = (float*)d_out;

    __half *xh, *wqh, *wkvh, *woh, *qh, *kvh, *yh;
    cudaGetSymbolAddress((void**)&xh,   g_xh);
    cudaGetSymbolAddress((void**)&wqh,  g_wqh);
    cudaGetSymbolAddress((void**)&wkvh, g_wkvh);
    cudaGetSymbolAddress((void**)&woh,  g_woh);
    cudaGetSymbolAddress((void**)&qh,   g_qh);
    cudaGetSymbolAddress((void**)&kvh,  g_kvh);
    cudaGetSymbolAddress((void**)&yh,   g_yh);

    cudaFuncSetAttribute(proj_fused, cudaFuncAttributeMaxDynamicSharedMemorySize, GSMEM);
    cudaFuncSetAttribute(f16_gemm_pipe, cudaFuncAttributeMaxDynamicSharedMemorySize, GSMEM);
    cudaFuncSetAttribute(flash_h, cudaFuncAttributeMaxDynamicSharedMemorySize,
                         FLASH_SMEM_BYTES);

    dim3 blk(256);
    // One fused fp32 -> fp16 convert for x + all weights
    cvt_all<<<(C_TOT + 255) / 256, blk>>>(x, Wq, Wk, Wv, Wo, xh, wqh, wkvh, woh);

    // Merged Q + KV projection with fused RoPE + RMSNorm epilogue
    proj_fused<<<dim3(20, MROWS / 128), blk, GSMEM>>>(xh, wqh, wkvh, qh, kvh, cosp, sinp);

    // Flash attention (fp16 mma.sync, BKV=128, LPT-ordered, cp.async KV)
    flash_h<<<dim3(T_ / 128, NH, B_), blk, FLASH_SMEM_BYTES>>>(qh, kvh, yh);

    // Output projection -> fp32 out
    f16_gemm_pipe<<<dim3(HID_ / 128, MROWS / 128), blk, GSMEM>>>(yh, woh, out, MROWS, HID_, HID_);
}